// round 14
// baseline (speedup 1.0000x reference)
#include <cuda_runtime.h>

namespace {
constexpr int T_ = 1024;
constexpr int S_ = 512;
constexpr int D_ = 32;
constexpr int K_ = 64;
constexpr float LOG2PI_F = 1.8378770664093453f;
constexpr float SHIFT = 72.0f;   // shift log-probs into comfortable fp32 range
}

// Per-sequence log-denominator accumulators (fp64 for a stable final sum).
__device__ double g_logden[S_];

__global__ void __launch_bounds__(K_) hmm_forward_kernel(
    const float* __restrict__ data,     // [T, S, D]
    const float* __restrict__ initp,    // [K]
    const float* __restrict__ trans,    // [K, K] row-stochastic
    const float* __restrict__ means,    // [K, D]
    const float* __restrict__ covars,   // [K, D]
    float* __restrict__ out)            // [S, K] alpha (+ scalar appended later)
{
    const int s = blockIdx.x;          // sequence
    const int k = threadIdx.x;         // state (0..63)
    const int lane = k & 31;
    const int warp = k >> 5;

    __shared__ __align__(16) float alpha_sh[K_];
    __shared__ __align__(16) float xs[D_];
    __shared__ float red[2];

    // ---- per-state Gaussian parameters in registers ----
    // logp_k(x) = sum_d x*( -0.5*inv*x + mu*inv ) + ck,
    // ck = -0.5*(sum mu^2*inv + sum log cov + D*log 2pi) + SHIFT
    float c1[D_], c2[D_];
    float sq = 0.f, ld = 0.f;
    const float4* mrow = reinterpret_cast<const float4*>(means + k * D_);
    const float4* crow = reinterpret_cast<const float4*>(covars + k * D_);
#pragma unroll
    for (int q = 0; q < D_ / 4; ++q) {
        float4 mv = mrow[q];
        float4 cv = crow[q];
        float i0 = 1.0f / cv.x, i1 = 1.0f / cv.y, i2 = 1.0f / cv.z, i3 = 1.0f / cv.w;
        c1[4*q+0] = -0.5f * i0;  c2[4*q+0] = mv.x * i0;
        c1[4*q+1] = -0.5f * i1;  c2[4*q+1] = mv.y * i1;
        c1[4*q+2] = -0.5f * i2;  c2[4*q+2] = mv.z * i2;
        c1[4*q+3] = -0.5f * i3;  c2[4*q+3] = mv.w * i3;
        sq += mv.x * mv.x * i0 + mv.y * mv.y * i1 + mv.z * mv.z * i2 + mv.w * mv.w * i3;
        ld += __logf(cv.x) + __logf(cv.y) + __logf(cv.z) + __logf(cv.w);
    }
    const float ck = -0.5f * (sq + ld + (float)D_ * LOG2PI_F) + SHIFT;

    // Transition column k in registers: (alpha @ A)[k] = sum_j alpha[j]*A[j][k]
    float Acol[K_];
#pragma unroll
    for (int j = 0; j < K_; ++j) Acol[j] = __ldg(trans + j * K_ + k);

    // Prefetch x for t=0 (128B, 16B-aligned)
    if (k < D_ / 4)
        reinterpret_cast<float4*>(xs)[k] =
            reinterpret_cast<const float4*>(data + (size_t)s * D_)[k];

    double logden = 0.0;
    float mk = initp[k];   // t=0 uses initial_probs in place of the matvec
    float alast = 0.0f;
    __syncthreads();

    for (int t = 0; t < T_; ++t) {
        // --- emission log-prob for (t, s, k) ---
        float lp0 = ck, lp1 = 0.f, lp2 = 0.f, lp3 = 0.f;
        const float4* x4 = reinterpret_cast<const float4*>(xs);
#pragma unroll
        for (int q = 0; q < D_ / 4; ++q) {
            float4 xv = x4[q];
            lp0 = fmaf(xv.x, fmaf(c1[4*q+0], xv.x, c2[4*q+0]), lp0);
            lp1 = fmaf(xv.y, fmaf(c1[4*q+1], xv.y, c2[4*q+1]), lp1);
            lp2 = fmaf(xv.z, fmaf(c1[4*q+2], xv.z, c2[4*q+2]), lp2);
            lp3 = fmaf(xv.w, fmaf(c1[4*q+3], xv.w, c2[4*q+3]), lp3);
        }
        float p = __expf((lp0 + lp1) + (lp2 + lp3));
        float a = p * mk;

        // --- block reduction: d = sum_k a_k ---
        float wsum = a;
#pragma unroll
        for (int off = 16; off; off >>= 1)
            wsum += __shfl_xor_sync(0xffffffffu, wsum, off);
        if (lane == 0) red[warp] = wsum;
        __syncthreads();                              // (A)
        float dsum = red[0] + red[1];
        float rinv = __fdividef(1.0f, dsum);
        alast = a * rinv;
        alpha_sh[k] = alast;
        logden += (double)(__logf(dsum) - SHIFT);

        // prefetch x for t+1 (xs reads for t finished before barrier A)
        if (k < D_ / 4 && t + 1 < T_)
            reinterpret_cast<float4*>(xs)[k] =
                reinterpret_cast<const float4*>(data + ((size_t)(t + 1) * S_ + s) * D_)[k];
        __syncthreads();                              // (B)

        // --- matvec for next step: mk = (alpha @ A)[k] ---
        if (t + 1 < T_) {
            float m0 = 0.f, m1 = 0.f, m2 = 0.f, m3 = 0.f;
            const float4* al4 = reinterpret_cast<const float4*>(alpha_sh);
#pragma unroll
            for (int jj = 0; jj < K_ / 4; ++jj) {
                float4 av = al4[jj];
                m0 = fmaf(av.x, Acol[4*jj+0], m0);
                m1 = fmaf(av.y, Acol[4*jj+1], m1);
                m2 = fmaf(av.z, Acol[4*jj+2], m2);
                m3 = fmaf(av.w, Acol[4*jj+3], m3);
            }
            mk = (m0 + m1) + (m2 + m3);
        }
    }

    out[(size_t)s * K_ + k] = alast;
    if (k == 0) g_logden[s] = logden;
}

// Deterministic final reduction: nll = -sum_s logden[s]
__global__ void hmm_reduce_kernel(float* __restrict__ out, int out_size)
{
    __shared__ double sh[S_];
    int t = threadIdx.x;
    sh[t] = g_logden[t];
    __syncthreads();
#pragma unroll
    for (int off = S_ / 2; off > 0; off >>= 1) {
        if (t < off) sh[t] += sh[t + off];
        __syncthreads();
    }
    if (t == 0 && out_size > S_ * K_)
        out[S_ * K_] = (float)(-sh[0]);
}

extern "C" void kernel_launch(void* const* d_in, const int* in_sizes, int n_in,
                              void* d_out, int out_size)
{
    const float* data   = (const float*)d_in[0];
    const float* initp  = (const float*)d_in[1];
    const float* trans  = (const float*)d_in[2];
    const float* means  = (const float*)d_in[3];
    const float* covars = (const float*)d_in[4];
    float* out = (float*)d_out;

    hmm_forward_kernel<<<S_, K_>>>(data, initp, trans, means, covars, out);
    hmm_reduce_kernel<<<1, S_>>>(out, out_size);
}